// round 1
// baseline (speedup 1.0000x reference)
#include <cuda_runtime.h>

// Problem constants (fixed by the reference)
constexpr int B  = 8;
constexpr int C  = 256;
constexpr int H  = 64;
constexpr int W  = 64;
constexpr int WC = 16;          // weight channels
constexpr int G  = C / WC;      // 16 groups sharing each weight
constexpr int HW = H * W;       // 4096

// out[b, g*WC+wc, oh, ow] = sum_{i,j in 3x3} x[b, g*WC+wc, oh+i-1, ow+j-1] * w[b, wc, i*3+j, oh*W+ow]
// One thread = one (b, wc, pixel); loops over the 16 groups, reusing the 9
// weights from registers. All loads/stores coalesced along ow.
__global__ __launch_bounds__(256) void agg_kernel(
    const float* __restrict__ x,
    const float* __restrict__ w,
    float* __restrict__ out)
{
    const int idx = blockIdx.x * blockDim.x + threadIdx.x;   // 0 .. B*WC*HW-1 = 2^19-1
    const int p  = idx & (HW - 1);          // pixel within plane
    const int wc = (idx >> 12) & (WC - 1);  // weight channel
    const int b  = idx >> 16;               // batch
    const int oh = p >> 6;
    const int ow = p & (W - 1);

    // Load the 9 weights for this (b, wc, pixel) once.
    float wv[9];
    const float* wp = w + ((size_t)(b * WC + wc) * 9) * HW + p;
    #pragma unroll
    for (int t = 0; t < 9; t++) wv[t] = wp[(size_t)t * HW];

    // Boundary predicates (pad = 1)
    const bool ym = (oh > 0);
    const bool yp = (oh < H - 1);
    const bool xm = (ow > 0);
    const bool xq = (ow < W - 1);

    const float* xbase = x   + (size_t)(b * C + wc) * HW + p;  // group 0 center pixel
    float*       obase = out + (size_t)(b * C + wc) * HW + p;

    #pragma unroll 4
    for (int g = 0; g < G; g++) {
        const float* xc = xbase + (size_t)g * WC * HW;  // center pixel of this channel plane
        float acc = 0.0f;

        // row above
        if (ym) {
            const float* r = xc - W;
            if (xm) acc += r[-1] * wv[0];
                    acc += r[ 0] * wv[1];
            if (xq) acc += r[ 1] * wv[2];
        }
        // center row
        {
            const float* r = xc;
            if (xm) acc += r[-1] * wv[3];
                    acc += r[ 0] * wv[4];
            if (xq) acc += r[ 1] * wv[5];
        }
        // row below
        if (yp) {
            const float* r = xc + W;
            if (xm) acc += r[-1] * wv[6];
                    acc += r[ 0] * wv[7];
            if (xq) acc += r[ 1] * wv[8];
        }

        obase[(size_t)g * WC * HW] = acc;
    }
}

extern "C" void kernel_launch(void* const* d_in, const int* in_sizes, int n_in,
                              void* d_out, int out_size)
{
    const float* x = (const float*)d_in[0];   // (8,256,64,64) f32
    const float* w = (const float*)d_in[1];   // (8,16,9,4096) f32
    float* out = (float*)d_out;               // (8,256,64,64) f32

    const int total = B * WC * HW;            // 524288 threads
    agg_kernel<<<total / 256, 256>>>(x, w, out);
}

// round 2
// speedup vs baseline: 1.6042x; 1.6042x over previous
#include <cuda_runtime.h>

// Problem constants (fixed by the reference)
constexpr int B  = 8;
constexpr int C  = 256;
constexpr int H  = 64;
constexpr int W  = 64;
constexpr int WC = 16;          // weight channels
constexpr int G  = C / WC;      // 16 groups sharing each weight
constexpr int HW = H * W;       // 4096
constexpr int Q  = HW / 4;      // float4 pixel-quads per plane = 1024

// out[b, g*WC+wc, oh, ow] = sum_{3x3 taps} x[b, g*WC+wc, oh+i-1, ow+j-1] * w[b, wc, i*3+j, oh*W+ow]
//
// One thread = one (b, wc, 4-pixel quad). The 9 per-pixel weights are loaded
// once as float4 and reused across all 16 groups. x rows are loaded as
// aligned float4; the +/-1 column neighbors come from warp shuffles (a warp
// spans exactly two 64-pixel rows, 16 lanes each, so row edges align with
// lane%16 boundaries and never cross warps).
__global__ __launch_bounds__(256) void agg_kernel_v2(
    const float* __restrict__ x,
    const float* __restrict__ w,
    float* __restrict__ out)
{
    const int idx = blockIdx.x * blockDim.x + threadIdx.x;  // 0 .. B*WC*Q-1
    const int q   = idx & (Q - 1);          // quad index within plane
    const int wc  = (idx >> 10) & (WC - 1);
    const int b   = idx >> 14;
    const int p4  = q << 2;                 // first pixel of the quad
    const int oh  = q >> 4;                 // 16 quads per row

    const bool rowL = ((q & 15) == 0);      // quad starts at ow=0
    const bool rowR = ((q & 15) == 15);     // quad ends at ow=63
    const bool ym   = (oh > 0);
    const bool yp   = (oh < H - 1);

    // 9 weight vectors for this (b, wc, quad), one float4 per tap.
    const float4* wp = (const float4*)(w + ((size_t)(b * WC + wc) * 9) * HW + p4);
    float4 wv[9];
    #pragma unroll
    for (int t = 0; t < 9; t++) wv[t] = wp[(size_t)t * Q];

    const float* xbase = x   + (size_t)(b * C + wc) * HW + p4;
    float*       obase = out + (size_t)(b * C + wc) * HW + p4;

    const float4 z4 = make_float4(0.f, 0.f, 0.f, 0.f);

    #pragma unroll 4
    for (int g = 0; g < G; g++) {
        const float* xc = xbase + (size_t)g * WC * HW;
        float4 acc = z4;

        #pragma unroll
        for (int r = 0; r < 3; r++) {
            const bool valid = (r == 0) ? ym : (r == 2) ? yp : true;
            float4 c = valid ? *(const float4*)(xc + (r - 1) * W) : z4;

            // Horizontal neighbors via shuffle (uniform across the warp).
            float lf = __shfl_up_sync(0xffffffffu, c.w, 1);
            float rt = __shfl_down_sync(0xffffffffu, c.x, 1);
            if (rowL) lf = 0.f;
            if (rowR) rt = 0.f;

            const float4 wl = wv[3 * r + 0];
            const float4 wm = wv[3 * r + 1];
            const float4 wr = wv[3 * r + 2];

            acc.x += lf  * wl.x + c.x * wm.x + c.y * wr.x;
            acc.y += c.x * wl.y + c.y * wm.y + c.z * wr.y;
            acc.z += c.y * wl.z + c.z * wm.z + c.w * wr.z;
            acc.w += c.z * wl.w + c.w * wm.w + rt  * wr.w;
        }

        *(float4*)(obase + (size_t)g * WC * HW) = acc;
    }
}

extern "C" void kernel_launch(void* const* d_in, const int* in_sizes, int n_in,
                              void* d_out, int out_size)
{
    const float* x = (const float*)d_in[0];   // (8,256,64,64) f32
    const float* w = (const float*)d_in[1];   // (8,16,9,4096) f32
    float* out = (float*)d_out;               // (8,256,64,64) f32

    const int total = B * WC * Q;             // 131072 threads
    agg_kernel_v2<<<total / 256, 256>>>(x, w, out);
}

// round 3
// speedup vs baseline: 1.9535x; 1.2178x over previous
#include <cuda_runtime.h>

// Problem constants (fixed by the reference)
constexpr int B  = 8;
constexpr int C  = 256;
constexpr int H  = 64;
constexpr int W  = 64;
constexpr int WC = 16;          // weight channels
constexpr int G  = C / WC;      // 16 groups sharing each weight
constexpr int HW = H * W;       // 4096
constexpr int Q  = HW / 4;      // float4 pixel-quads per plane = 1024

// One thread = one (b, wc, 4-pixel quad) over all 16 groups.
// Groups are processed in 4 blocks of 4; each block front-batches its
// 12 row loads (LDG.128) into registers before any FFMA, maximizing
// memory-level parallelism. launch_bounds(256,2) allows ~128 regs so
// the batch stays register-resident.
__global__ __launch_bounds__(256, 2) void agg_kernel_v3(
    const float* __restrict__ x,
    const float* __restrict__ w,
    float* __restrict__ out)
{
    const int idx = blockIdx.x * blockDim.x + threadIdx.x;  // 0 .. B*WC*Q-1
    const int q   = idx & (Q - 1);          // quad index within plane
    const int wc  = (idx >> 10) & (WC - 1);
    const int b   = idx >> 14;
    const int p4  = q << 2;                 // first pixel of the quad
    const int oh  = q >> 4;                 // 16 quads per row

    const bool rowL = ((q & 15) == 0);      // quad starts at ow=0
    const bool rowR = ((q & 15) == 15);     // quad ends at ow=63
    const bool ym   = (oh > 0);
    const bool yp   = (oh < H - 1);

    // 9 weight vectors for this (b, wc, quad), one float4 per tap.
    const float4* wp = (const float4*)(w + ((size_t)(b * WC + wc) * 9) * HW + p4);
    float4 wv[9];
    #pragma unroll
    for (int t = 0; t < 9; t++) wv[t] = wp[(size_t)t * Q];

    const float* xbase = x   + (size_t)(b * C + wc) * HW + p4;
    float*       obase = out + (size_t)(b * C + wc) * HW + p4;

    const float4 z4 = make_float4(0.f, 0.f, 0.f, 0.f);

    #pragma unroll
    for (int blk = 0; blk < 4; blk++) {
        // ---- Phase 1: batch-load 12 rows (4 groups x 3 rows), all independent.
        float4 c[4][3];
        #pragma unroll
        for (int gg = 0; gg < 4; gg++) {
            const float* xc = xbase + (size_t)(blk * 4 + gg) * WC * HW;
            c[gg][0] = ym ? *(const float4*)(xc - W) : z4;
            c[gg][1] =      *(const float4*)(xc);
            c[gg][2] = yp ? *(const float4*)(xc + W) : z4;
        }

        // ---- Phase 2: compute + store each group.
        #pragma unroll
        for (int gg = 0; gg < 4; gg++) {
            float4 acc = z4;
            #pragma unroll
            for (int r = 0; r < 3; r++) {
                const float4 cc = c[gg][r];
                float lf = __shfl_up_sync(0xffffffffu, cc.w, 1);
                float rt = __shfl_down_sync(0xffffffffu, cc.x, 1);
                if (rowL) lf = 0.f;
                if (rowR) rt = 0.f;

                const float4 wl = wv[3 * r + 0];
                const float4 wm = wv[3 * r + 1];
                const float4 wr = wv[3 * r + 2];

                acc.x += lf   * wl.x + cc.x * wm.x + cc.y * wr.x;
                acc.y += cc.x * wl.y + cc.y * wm.y + cc.z * wr.y;
                acc.z += cc.y * wl.z + cc.z * wm.z + cc.w * wr.z;
                acc.w += cc.z * wl.w + cc.w * wm.w + rt   * wr.w;
            }
            *(float4*)(obase + (size_t)(blk * 4 + gg) * WC * HW) = acc;
        }
    }
}

extern "C" void kernel_launch(void* const* d_in, const int* in_sizes, int n_in,
                              void* d_out, int out_size)
{
    const float* x = (const float*)d_in[0];   // (8,256,64,64) f32
    const float* w = (const float*)d_in[1];   // (8,16,9,4096) f32
    float* out = (float*)d_out;               // (8,256,64,64) f32

    const int total = B * WC * Q;             // 131072 threads
    agg_kernel_v3<<<total / 256, 256>>>(x, w, out);
}

// round 4
// speedup vs baseline: 2.0352x; 1.0419x over previous
#include <cuda_runtime.h>

// Problem constants (fixed by the reference)
constexpr int B  = 8;
constexpr int C  = 256;
constexpr int H  = 64;
constexpr int W  = 64;
constexpr int WC = 16;          // weight channels
constexpr int G  = C / WC;      // 16 groups sharing each weight
constexpr int HW = H * W;       // 4096
constexpr int Q  = HW / 4;      // float4 pixel-quads per plane = 1024

// One thread = one (b, wc, 4-pixel quad) over all 16 groups.
// Groups are processed in 4 blocks of 4; each block front-batches its
// 12 row loads (LDG.128) into registers before any FFMA, maximizing
// memory-level parallelism. launch_bounds(256,2) allows ~128 regs so
// the batch stays register-resident.
__global__ __launch_bounds__(256, 2) void agg_kernel_v3(
    const float* __restrict__ x,
    const float* __restrict__ w,
    float* __restrict__ out)
{
    const int idx = blockIdx.x * blockDim.x + threadIdx.x;  // 0 .. B*WC*Q-1
    const int q   = idx & (Q - 1);          // quad index within plane
    const int wc  = (idx >> 10) & (WC - 1);
    const int b   = idx >> 14;
    const int p4  = q << 2;                 // first pixel of the quad
    const int oh  = q >> 4;                 // 16 quads per row

    const bool rowL = ((q & 15) == 0);      // quad starts at ow=0
    const bool rowR = ((q & 15) == 15);     // quad ends at ow=63
    const bool ym   = (oh > 0);
    const bool yp   = (oh < H - 1);

    // 9 weight vectors for this (b, wc, quad), one float4 per tap.
    const float4* wp = (const float4*)(w + ((size_t)(b * WC + wc) * 9) * HW + p4);
    float4 wv[9];
    #pragma unroll
    for (int t = 0; t < 9; t++) wv[t] = wp[(size_t)t * Q];

    const float* xbase = x   + (size_t)(b * C + wc) * HW + p4;
    float*       obase = out + (size_t)(b * C + wc) * HW + p4;

    const float4 z4 = make_float4(0.f, 0.f, 0.f, 0.f);

    #pragma unroll
    for (int blk = 0; blk < 4; blk++) {
        // ---- Phase 1: batch-load 12 rows (4 groups x 3 rows), all independent.
        float4 c[4][3];
        #pragma unroll
        for (int gg = 0; gg < 4; gg++) {
            const float* xc = xbase + (size_t)(blk * 4 + gg) * WC * HW;
            c[gg][0] = ym ? *(const float4*)(xc - W) : z4;
            c[gg][1] =      *(const float4*)(xc);
            c[gg][2] = yp ? *(const float4*)(xc + W) : z4;
        }

        // ---- Phase 2: compute + store each group.
        #pragma unroll
        for (int gg = 0; gg < 4; gg++) {
            float4 acc = z4;
            #pragma unroll
            for (int r = 0; r < 3; r++) {
                const float4 cc = c[gg][r];
                float lf = __shfl_up_sync(0xffffffffu, cc.w, 1);
                float rt = __shfl_down_sync(0xffffffffu, cc.x, 1);
                if (rowL) lf = 0.f;
                if (rowR) rt = 0.f;

                const float4 wl = wv[3 * r + 0];
                const float4 wm = wv[3 * r + 1];
                const float4 wr = wv[3 * r + 2];

                acc.x += lf   * wl.x + cc.x * wm.x + cc.y * wr.x;
                acc.y += cc.x * wl.y + cc.y * wm.y + cc.z * wr.y;
                acc.z += cc.y * wl.z + cc.z * wm.z + cc.w * wr.z;
                acc.w += cc.z * wl.w + cc.w * wm.w + rt   * wr.w;
            }
            *(float4*)(obase + (size_t)(blk * 4 + gg) * WC * HW) = acc;
        }
    }
}

extern "C" void kernel_launch(void* const* d_in, const int* in_sizes, int n_in,
                              void* d_out, int out_size)
{
    const float* x = (const float*)d_in[0];   // (8,256,64,64) f32
    const float* w = (const float*)d_in[1];   // (8,16,9,4096) f32
    float* out = (float*)d_out;               // (8,256,64,64) f32

    const int total = B * WC * Q;             // 131072 threads
    agg_kernel_v3<<<total / 256, 256>>>(x, w, out);
}